// round 3
// baseline (speedup 1.0000x reference)
#include <cuda_runtime.h>
#include <cstdint>
#include <cfloat>

#define N_NODES_MAX 100000
#define N_EDGES_MAX 1600000
#define FULL 0xFFFFFFFFu

// ---------------- scratch (static device globals) ---------------------------
__device__ float4  g_h[N_NODES_MAX * 16];     // [N,64] projected features
__device__ float4  g_el[N_NODES_MAX];         // [N,4]
__device__ float4  g_er[N_NODES_MAX];         // [N,4]
__device__ int     g_cnt[N_NODES_MAX];        // in-degree
__device__ int     g_fill[N_NODES_MAX];       // scatter cursors
__device__ int     g_rowptr[N_NODES_MAX];     // exclusive prefix of cnt
__device__ int     g_blksum[128];
__device__ int     g_esrc[N_EDGES_MAX];       // CSR: src node per slot

__device__ __forceinline__ float leaky(float x) { return x > 0.f ? x : 0.2f * x; }

// ---------------- kernel: zero counters -------------------------------------
__global__ void zero_kernel(int n_nodes) {
    int i = blockIdx.x * blockDim.x + threadIdx.x;
    if (i < n_nodes) { g_cnt[i] = 0; g_fill[i] = 0; }
}

// ---------------- kernel: in-degree histogram -------------------------------
__global__ void hist_kernel(const int* __restrict__ dst, int n_edges) {
    int e = blockIdx.x * blockDim.x + threadIdx.x;
    if (e < n_edges) atomicAdd(&g_cnt[dst[e]], 1);
}

// ---------------- scan (3 kernels): rowptr = exclusive_scan(cnt) ------------
__global__ __launch_bounds__(1024) void scan1_kernel(int n) {
    __shared__ int sh[1024];
    int i = blockIdx.x * 1024 + threadIdx.x;
    int v = (i < n) ? g_cnt[i] : 0;
    sh[threadIdx.x] = v;
    __syncthreads();
    for (int off = 1; off < 1024; off <<= 1) {
        int t = (threadIdx.x >= off) ? sh[threadIdx.x - off] : 0;
        __syncthreads();
        sh[threadIdx.x] += t;
        __syncthreads();
    }
    if (i < n) g_rowptr[i] = sh[threadIdx.x] - v;
    if (threadIdx.x == 1023) g_blksum[blockIdx.x] = sh[1023];
}
__global__ void scan2_kernel(int nb) {
    __shared__ int sh[128];
    int t = threadIdx.x;
    int v = (t < nb) ? g_blksum[t] : 0;
    sh[t] = v;
    __syncthreads();
    for (int off = 1; off < 128; off <<= 1) {
        int u = (t >= off) ? sh[t - off] : 0;
        __syncthreads();
        sh[t] += u;
        __syncthreads();
    }
    if (t < nb) g_blksum[t] = sh[t] - v;   // exclusive
}
__global__ __launch_bounds__(1024) void scan3_kernel(int n) {
    int i = blockIdx.x * 1024 + threadIdx.x;
    if (i < n) g_rowptr[i] += g_blksum[blockIdx.x];
}

// ---------------- kernel: CSR scatter ----------------------------------------
__global__ void scatter_kernel(const int* __restrict__ src,
                               const int* __restrict__ dst, int n_edges) {
    int e = blockIdx.x * blockDim.x + threadIdx.x;
    if (e >= n_edges) return;
    int d = dst[e];
    int r = atomicAdd(&g_fill[d], 1);
    g_esrc[g_rowptr[d] + r] = src[e];
}

// ---------------- kernel: h = feat @ W, el/er --------------------------------
#define GEMM_SMEM_FLOATS (128 * 64 + 64 + 64 + 128 * 129)
__global__ __launch_bounds__(128)
void gemm_kernel(const float* __restrict__ feat, const float* __restrict__ W,
                 const float* __restrict__ attn_l, const float* __restrict__ attn_r,
                 int n_nodes) {
    extern __shared__ float smem[];
    float* Wsh   = smem;
    float* alS   = smem + 8192;
    float* arS   = smem + 8256;
    float* featS = smem + 8320;

    const int tid  = threadIdx.x;
    const int base = blockIdx.x * 128;

    for (int i = tid; i < 128 * 64; i += 128) Wsh[i] = W[i];
    if (tid < 64) { alS[tid] = attn_l[tid]; arS[tid] = attn_r[tid]; }
    for (int i = tid; i < 128 * 128; i += 128) {
        int row = i >> 7, col = i & 127;
        int node = base + row;
        featS[row * 129 + col] = (node < n_nodes) ? feat[node * 128 + col] : 0.f;
    }
    __syncthreads();

    float acc[64];
#pragma unroll
    for (int c = 0; c < 64; c++) acc[c] = 0.f;

    const float4* Wsh4 = (const float4*)Wsh;
    for (int k = 0; k < 128; k++) {
        float f = featS[tid * 129 + k];
#pragma unroll
        for (int c4 = 0; c4 < 16; c4++) {
            float4 w = Wsh4[k * 16 + c4];
            acc[c4 * 4 + 0] += f * w.x;
            acc[c4 * 4 + 1] += f * w.y;
            acc[c4 * 4 + 2] += f * w.z;
            acc[c4 * 4 + 3] += f * w.w;
        }
    }

    float el_[4], er_[4];
#pragma unroll
    for (int hd = 0; hd < 4; hd++) {
        float sl = 0.f, sr = 0.f;
#pragma unroll
        for (int d = 0; d < 16; d++) {
            sl += acc[hd * 16 + d] * alS[hd * 16 + d];
            sr += acc[hd * 16 + d] * arS[hd * 16 + d];
        }
        el_[hd] = sl; er_[hd] = sr;
    }

    const int node = base + tid;
    if (node < n_nodes) {
        g_el[node] = make_float4(el_[0], el_[1], el_[2], el_[3]);
        g_er[node] = make_float4(er_[0], er_[1], er_[2], er_[3]);
    }

    __syncthreads();
#pragma unroll
    for (int c = 0; c < 64; c++) featS[tid * 65 + c] = acc[c];
    __syncthreads();
    float* g_h_f = (float*)g_h;
    for (int i = tid; i < 128 * 64; i += 128) {
        int row = i >> 6, col = i & 63;
        int nd = base + row;
        if (nd < n_nodes) g_h_f[nd * 64 + col] = featS[row * 65 + col];
    }
}

// ---------------- kernel: fused softmax + aggregation, single pass -----------
// one warp per node; lane owns output cols 2*lane..2*lane+1, head = lane>>3.
// Softmax shift-invariance => no max subtraction needed (logits bounded ~|10|).
// Every lane accumulates the full denominator for its head (no reduction).
__global__ __launch_bounds__(256)
void node_kernel(const float* __restrict__ bias, float* __restrict__ out,
                 int n_nodes) {
    const int gwarp = (blockIdx.x * blockDim.x + threadIdx.x) >> 5;
    const int lane  = threadIdx.x & 31;
    if (gwarp >= n_nodes) return;

    const int base = g_rowptr[gwarp];
    const int deg  = g_cnt[gwarp];
    const int hd   = lane >> 3;

    const float2 b2 = ((const float2*)bias)[lane];
    float2* outp = (float2*)out + (gwarp * 32 + lane);

    if (deg == 0) { *outp = b2; return; }

    const float er_h = ((const float*)g_er)[gwarp * 4 + hd];
    const float* elf = (const float*)g_el;
    const float2* h2 = (const float2*)g_h;

    float2 acc = make_float2(0.f, 0.f);
    float  den = 0.f;

    const int nb = (deg + 31) >> 5;
    for (int b = 0; b < nb; b++) {
        const int off = b * 32;
        const int cnt = min(32, deg - off);
        // coalesced batch load of up to 32 edge sources into registers
        int s_reg = (off + lane < deg) ? g_esrc[base + off + lane] : 0;
#pragma unroll 4
        for (int i = 0; i < cnt; i++) {
            int s = __shfl_sync(FULL, s_reg, i);
            float ex = __expf(leaky(elf[s * 4 + hd] + er_h));
            float2 v = h2[s * 32 + lane];
            acc.x += ex * v.x;
            acc.y += ex * v.y;
            den   += ex;
        }
    }

    const float rd = 1.f / den;
    *outp = make_float2(acc.x * rd + b2.x, acc.y * rd + b2.y);
}

// ---------------- launcher --------------------------------------------------
extern "C" void kernel_launch(void* const* d_in, const int* in_sizes, int n_in,
                              void* d_out, int out_size) {
    const float* feat   = (const float*)d_in[0];
    const float* W      = (const float*)d_in[1];
    const float* attn_l = (const float*)d_in[2];
    const float* attn_r = (const float*)d_in[3];
    const float* bias   = (const float*)d_in[4];
    const int*   src    = (const int*)d_in[5];
    const int*   dst    = (const int*)d_in[6];
    float*       out    = (float*)d_out;

    const int n_nodes = in_sizes[0] / 128;
    const int n_edges = in_sizes[5];
    const int nb      = (n_nodes + 1023) / 1024;

    cudaFuncSetAttribute(gemm_kernel, cudaFuncAttributeMaxDynamicSharedMemorySize,
                         GEMM_SMEM_FLOATS * (int)sizeof(float));

    zero_kernel<<<(n_nodes + 255) / 256, 256>>>(n_nodes);
    hist_kernel<<<(n_edges + 255) / 256, 256>>>(dst, n_edges);
    scan1_kernel<<<nb, 1024>>>(n_nodes);
    scan2_kernel<<<1, 128>>>(nb);
    scan3_kernel<<<nb, 1024>>>(n_nodes);
    scatter_kernel<<<(n_edges + 255) / 256, 256>>>(src, dst, n_edges);
    gemm_kernel<<<(n_nodes + 127) / 128, 128,
                  GEMM_SMEM_FLOATS * (int)sizeof(float)>>>(feat, W, attn_l,
                                                           attn_r, n_nodes);
    node_kernel<<<(n_nodes * 32 + 255) / 256, 256>>>(bias, out, n_nodes);
}

// round 5
// speedup vs baseline: 1.0342x; 1.0342x over previous
#include <cuda_runtime.h>
#include <cstdint>
#include <cfloat>

#define N_NODES_MAX 100000
#define N_EDGES_MAX 1600000
#define FULL 0xFFFFFFFFu

typedef unsigned long long ull;

// ---------------- scratch (static device globals) ---------------------------
__device__ float4  g_h[N_NODES_MAX * 16];     // [N,64] projected features
__device__ float4  g_el[N_NODES_MAX];         // [N,4]
__device__ float4  g_er[N_NODES_MAX];         // [N,4]
__device__ int     g_cnt[N_NODES_MAX];        // in-degree
__device__ int     g_fill[N_NODES_MAX];       // scatter cursors
__device__ int     g_rowptr[N_NODES_MAX];     // exclusive prefix of cnt
__device__ int     g_blksum[128];
__device__ int     g_esrc[N_EDGES_MAX];       // CSR: src node per slot

__device__ __forceinline__ float leaky(float x) { return x > 0.f ? x : 0.2f * x; }

__device__ __forceinline__ ull pack2(float f) {
    ull r;
    asm("mov.b64 %0, {%1, %1};" : "=l"(r) : "f"(f));
    return r;
}
__device__ __forceinline__ void fma2(ull& acc, ull a, ull b) {
    asm("fma.rn.f32x2 %0, %1, %2, %0;" : "+l"(acc) : "l"(a), "l"(b));
}
__device__ __forceinline__ void unpack2(ull v, float& lo, float& hi) {
    asm("mov.b64 {%0, %1}, %2;" : "=f"(lo), "=f"(hi) : "l"(v));
}

// ---------------- kernel: zero counters -------------------------------------
__global__ void zero_kernel(int n_nodes) {
    int i = blockIdx.x * blockDim.x + threadIdx.x;
    if (i < n_nodes) { g_cnt[i] = 0; g_fill[i] = 0; }
}

// ---------------- kernel: in-degree histogram -------------------------------
__global__ void hist_kernel(const int* __restrict__ dst, int n_edges) {
    int e = blockIdx.x * blockDim.x + threadIdx.x;
    if (e < n_edges) atomicAdd(&g_cnt[dst[e]], 1);
}

// ---------------- scan (3 kernels): rowptr = exclusive_scan(cnt) ------------
__global__ __launch_bounds__(1024) void scan1_kernel(int n) {
    __shared__ int sh[1024];
    int i = blockIdx.x * 1024 + threadIdx.x;
    int v = (i < n) ? g_cnt[i] : 0;
    sh[threadIdx.x] = v;
    __syncthreads();
    for (int off = 1; off < 1024; off <<= 1) {
        int t = (threadIdx.x >= off) ? sh[threadIdx.x - off] : 0;
        __syncthreads();
        sh[threadIdx.x] += t;
        __syncthreads();
    }
    if (i < n) g_rowptr[i] = sh[threadIdx.x] - v;
    if (threadIdx.x == 1023) g_blksum[blockIdx.x] = sh[1023];
}
__global__ void scan2_kernel(int nb) {
    __shared__ int sh[128];
    int t = threadIdx.x;
    int v = (t < nb) ? g_blksum[t] : 0;
    sh[t] = v;
    __syncthreads();
    for (int off = 1; off < 128; off <<= 1) {
        int u = (t >= off) ? sh[t - off] : 0;
        __syncthreads();
        sh[t] += u;
        __syncthreads();
    }
    if (t < nb) g_blksum[t] = sh[t] - v;   // exclusive
}
__global__ __launch_bounds__(1024) void scan3_kernel(int n) {
    int i = blockIdx.x * 1024 + threadIdx.x;
    if (i < n) g_rowptr[i] += g_blksum[blockIdx.x];
}

// ---------------- kernel: CSR scatter ----------------------------------------
__global__ void scatter_kernel(const int* __restrict__ src,
                               const int* __restrict__ dst, int n_edges) {
    int e = blockIdx.x * blockDim.x + threadIdx.x;
    if (e >= n_edges) return;
    int d = dst[e];
    int r = atomicAdd(&g_fill[d], 1);
    g_esrc[g_rowptr[d] + r] = src[e];
}

// ---------------- kernel: h = feat @ W, el/er (f32x2 packed FMA) -------------
#define GEMM_SMEM_FLOATS (128 * 64 + 64 + 64 + 128 * 129)
__global__ __launch_bounds__(128)
void gemm_kernel(const float* __restrict__ feat, const float* __restrict__ W,
                 const float* __restrict__ attn_l, const float* __restrict__ attn_r,
                 int n_nodes) {
    extern __shared__ float smem[];
    float* Wsh   = smem;                   // 8192 floats (16B aligned)
    float* alS   = smem + 8192;            // 64
    float* arS   = smem + 8256;            // 64
    float* featS = smem + 8320;            // 128*129 input / 128*65 transpose

    const int tid  = threadIdx.x;
    const int base = blockIdx.x * 128;

    for (int i = tid; i < 128 * 64; i += 128) Wsh[i] = W[i];
    if (tid < 64) { alS[tid] = attn_l[tid]; arS[tid] = attn_r[tid]; }
    for (int i = tid; i < 128 * 128; i += 128) {
        int row = i >> 7, col = i & 127;
        int node = base + row;
        featS[row * 129 + col] = (node < n_nodes) ? feat[node * 128 + col] : 0.f;
    }
    __syncthreads();

    // 32 packed-f32x2 accumulators = 64 output columns
    ull acc2[32];
#pragma unroll
    for (int j = 0; j < 32; j++) acc2[j] = 0ull;

    const ulonglong2* WshV = (const ulonglong2*)Wsh;  // 16B = 4 cols per elem
    for (int k = 0; k < 128; k++) {
        ull f2 = pack2(featS[tid * 129 + k]);
#pragma unroll
        for (int j = 0; j < 16; j++) {
            ulonglong2 w = WshV[k * 16 + j];
            fma2(acc2[2 * j + 0], f2, w.x);
            fma2(acc2[2 * j + 1], f2, w.y);
        }
    }

    // done reading featS as input; reuse it (pad 65) as h-transpose buffer
    __syncthreads();
#pragma unroll
    for (int j = 0; j < 32; j++) {
        float lo, hi;
        unpack2(acc2[j], lo, hi);
        featS[tid * 65 + 2 * j + 0] = lo;
        featS[tid * 65 + 2 * j + 1] = hi;
    }

    // attention halves from own smem row (no sync needed for own writes)
    float el_[4], er_[4];
#pragma unroll
    for (int hd = 0; hd < 4; hd++) {
        float sl = 0.f, sr = 0.f;
#pragma unroll
        for (int d = 0; d < 16; d++) {
            float v = featS[tid * 65 + hd * 16 + d];
            sl += v * alS[hd * 16 + d];
            sr += v * arS[hd * 16 + d];
        }
        el_[hd] = sl; er_[hd] = sr;
    }

    const int node = base + tid;
    if (node < n_nodes) {
        g_el[node] = make_float4(el_[0], el_[1], el_[2], el_[3]);
        g_er[node] = make_float4(er_[0], er_[1], er_[2], er_[3]);
    }

    __syncthreads();
    float* g_h_f = (float*)g_h;
    for (int i = tid; i < 128 * 64; i += 128) {
        int row = i >> 6, col = i & 63;
        int nd = base + row;
        if (nd < n_nodes) g_h_f[nd * 64 + col] = featS[row * 65 + col];
    }
}

// ---------------- kernel: fused softmax + aggregation, single pass -----------
// one warp per node; lane owns output cols 2*lane..2*lane+1, head = lane>>3.
// Softmax shift-invariance => no max subtraction (logits bounded).
__global__ __launch_bounds__(256)
void node_kernel(const float* __restrict__ bias, float* __restrict__ out,
                 int n_nodes) {
    const int gwarp = (blockIdx.x * blockDim.x + threadIdx.x) >> 5;
    const int lane  = threadIdx.x & 31;
    if (gwarp >= n_nodes) return;

    const int base = g_rowptr[gwarp];
    const int deg  = g_cnt[gwarp];
    const int hd   = lane >> 3;

    const float2 b2 = ((const float2*)bias)[lane];
    float2* outp = (float2*)out + (gwarp * 32 + lane);

    if (deg == 0) { *outp = b2; return; }

    const float er_h = ((const float*)g_er)[gwarp * 4 + hd];
    const float* elf = (const float*)g_el;
    const float2* h2 = (const float2*)g_h;

    float2 acc = make_float2(0.f, 0.f);
    float  den = 0.f;

    const int nb = (deg + 31) >> 5;
    // software pipeline: batch b+1's sources prefetched while consuming b
    int s_reg = (lane < deg) ? g_esrc[base + lane] : 0;
    for (int b = 0; b < nb; b++) {
        const int cur = s_reg;
        const int noff = (b + 1) * 32;
        if (b + 1 < nb)
            s_reg = (noff + lane < deg) ? g_esrc[base + noff + lane] : 0;
        const int cnt = min(32, deg - b * 32);
#pragma unroll 8
        for (int i = 0; i < cnt; i++) {
            int s = __shfl_sync(FULL, cur, i);
            float ex = __expf(leaky(elf[s * 4 + hd] + er_h));
            float2 v = h2[s * 32 + lane];
            acc.x += ex * v.x;
            acc.y += ex * v.y;
            den   += ex;
        }
    }

    const float rd = 1.f / den;
    *outp = make_float2(acc.x * rd + b2.x, acc.y * rd + b2.y);
}

// ---------------- launcher --------------------------------------------------
extern "C" void kernel_launch(void* const* d_in, const int* in_sizes, int n_in,
                              void* d_out, int out_size) {
    const float* feat   = (const float*)d_in[0];
    const float* W      = (const float*)d_in[1];
    const float* attn_l = (const float*)d_in[2];
    const float* attn_r = (const float*)d_in[3];
    const float* bias   = (const float*)d_in[4];
    const int*   src    = (const int*)d_in[5];
    const int*   dst    = (const int*)d_in[6];
    float*       out    = (float*)d_out;

    const int n_nodes = in_sizes[0] / 128;
    const int n_edges = in_sizes[5];
    const int nb      = (n_nodes + 1023) / 1024;

    cudaFuncSetAttribute(gemm_kernel, cudaFuncAttributeMaxDynamicSharedMemorySize,
                         GEMM_SMEM_FLOATS * (int)sizeof(float));

    zero_kernel<<<(n_nodes + 255) / 256, 256>>>(n_nodes);
    hist_kernel<<<(n_edges + 255) / 256, 256>>>(dst, n_edges);
    scan1_kernel<<<nb, 1024>>>(n_nodes);
    scan2_kernel<<<1, 128>>>(nb);
    scan3_kernel<<<nb, 1024>>>(n_nodes);
    scatter_kernel<<<(n_edges + 255) / 256, 256>>>(src, dst, n_edges);
    gemm_kernel<<<(n_nodes + 127) / 128, 128,
                  GEMM_SMEM_FLOATS * (int)sizeof(float)>>>(feat, W, attn_l,
                                                           attn_r, n_nodes);
    node_kernel<<<(n_nodes * 32 + 255) / 256, 256>>>(bias, out, n_nodes);
}

// round 6
// speedup vs baseline: 1.2151x; 1.1749x over previous
#include <cuda_runtime.h>
#include <cstdint>
#include <cfloat>

#define N_NODES_MAX 100000
#define N_EDGES_MAX 1600000
#define FULL 0xFFFFFFFFu

typedef unsigned long long ull;

// ---------------- scratch (static device globals) ---------------------------
__device__ float4  g_h[N_NODES_MAX * 16];     // [N,64] projected features
__device__ float4  g_el[N_NODES_MAX];         // [N,4]
__device__ float4  g_er[N_NODES_MAX];         // [N,4]
__device__ int     g_cnt[N_NODES_MAX];        // in-degree
__device__ int     g_fill[N_NODES_MAX];       // scatter cursors
__device__ int     g_rowptr[N_NODES_MAX];     // exclusive prefix of cnt
__device__ int     g_blksum[128];
__device__ int     g_esrc[N_EDGES_MAX];       // CSR: src node per slot

__device__ __forceinline__ float leaky(float x) { return x > 0.f ? x : 0.2f * x; }

__device__ __forceinline__ ull pack2(float f) {
    ull r;
    asm("mov.b64 %0, {%1, %1};" : "=l"(r) : "f"(f));
    return r;
}
__device__ __forceinline__ void fma2(ull& acc, ull a, ull b) {
    asm("fma.rn.f32x2 %0, %1, %2, %0;" : "+l"(acc) : "l"(a), "l"(b));
}
__device__ __forceinline__ void unpack2(ull v, float& lo, float& hi) {
    asm("mov.b64 {%0, %1}, %2;" : "=f"(lo), "=f"(hi) : "l"(v));
}

// ---------------- kernel: zero counters -------------------------------------
__global__ void zero_kernel(int n_nodes) {
    int i = blockIdx.x * blockDim.x + threadIdx.x;
    if (i < n_nodes) { g_cnt[i] = 0; g_fill[i] = 0; }
}

// ---------------- kernel: in-degree histogram -------------------------------
__global__ void hist_kernel(const int* __restrict__ dst, int n_edges) {
    int e = blockIdx.x * blockDim.x + threadIdx.x;
    if (e < n_edges) atomicAdd(&g_cnt[dst[e]], 1);
}

// ---------------- scan (3 kernels): rowptr = exclusive_scan(cnt) ------------
__global__ __launch_bounds__(1024) void scan1_kernel(int n) {
    __shared__ int sh[1024];
    int i = blockIdx.x * 1024 + threadIdx.x;
    int v = (i < n) ? g_cnt[i] : 0;
    sh[threadIdx.x] = v;
    __syncthreads();
    for (int off = 1; off < 1024; off <<= 1) {
        int t = (threadIdx.x >= off) ? sh[threadIdx.x - off] : 0;
        __syncthreads();
        sh[threadIdx.x] += t;
        __syncthreads();
    }
    if (i < n) g_rowptr[i] = sh[threadIdx.x] - v;
    if (threadIdx.x == 1023) g_blksum[blockIdx.x] = sh[1023];
}
__global__ void scan2_kernel(int nb) {
    __shared__ int sh[128];
    int t = threadIdx.x;
    int v = (t < nb) ? g_blksum[t] : 0;
    sh[t] = v;
    __syncthreads();
    for (int off = 1; off < 128; off <<= 1) {
        int u = (t >= off) ? sh[t - off] : 0;
        __syncthreads();
        sh[t] += u;
        __syncthreads();
    }
    if (t < nb) g_blksum[t] = sh[t] - v;   // exclusive
}
__global__ __launch_bounds__(1024) void scan3_kernel(int n) {
    int i = blockIdx.x * 1024 + threadIdx.x;
    if (i < n) g_rowptr[i] += g_blksum[blockIdx.x];
}

// ---------------- kernel: CSR scatter ----------------------------------------
__global__ void scatter_kernel(const int* __restrict__ src,
                               const int* __restrict__ dst, int n_edges) {
    int e = blockIdx.x * blockDim.x + threadIdx.x;
    if (e >= n_edges) return;
    int d = dst[e];
    int r = atomicAdd(&g_fill[d], 1);
    g_esrc[g_rowptr[d] + r] = src[e];
}

// ---------------- kernel: h = feat @ W, el/er (register-tiled, f32x2) --------
// 256 threads, tile = 128 nodes x 64 cols. Thread (tx=tid&31, ty=tid>>5)
// computes nodes tx*4..+3, cols ty*8..+7. Per k-step: 3 LDS.128 + 16 FFMA2.
// smem floats: featT[128*128] (k-major) + Wsh[128*64] + al[64]+ar[64]
//              + elS[512] + erS[512]
#define GEMM_SMEM_FLOATS (128 * 128 + 128 * 64 + 64 + 64 + 512 + 512)
__global__ __launch_bounds__(256)
void gemm_kernel(const float* __restrict__ feat, const float* __restrict__ W,
                 const float* __restrict__ attn_l, const float* __restrict__ attn_r,
                 int n_nodes) {
    extern __shared__ float smem[];
    float* featT = smem;                       // [k][node] 128x128
    float* Wsh   = smem + 16384;               // [k][col]  128x64
    float* alS   = smem + 16384 + 8192;        // 64
    float* arS   = alS + 64;                   // 64
    float* elS   = arS + 64;                   // [node][head] 128x4
    float* erS   = elS + 512;                  // 128x4

    const int tid  = threadIdx.x;
    const int tx   = tid & 31;
    const int ty   = tid >> 5;
    const int base = blockIdx.x * 128;

    // load W (coalesced, row-major matches [k][col])
    for (int i = tid; i < 128 * 64; i += 256) Wsh[i] = W[i];
    if (tid < 64) { alS[tid] = attn_l[tid]; arS[tid] = attn_r[tid]; }
    if (tid < 128) {
        float4 z = make_float4(0.f, 0.f, 0.f, 0.f);
        ((float4*)elS)[tid] = z;
        ((float4*)erS)[tid] = z;
    }
    // transpose-load feat -> featT[k][node]; warp lanes cover consecutive
    // nodes (conflict-free STS), float4 global reads
    const float4* feat4 = (const float4*)feat;
    for (int i = tid; i < 128 * 32; i += 256) {
        int row = i & 127;           // node within tile (consecutive per warp)
        int c4  = i >> 7;            // k-group
        int node = base + row;
        float4 v = (node < n_nodes) ? feat4[node * 32 + c4]
                                    : make_float4(0.f, 0.f, 0.f, 0.f);
        featT[(c4 * 4 + 0) * 128 + row] = v.x;
        featT[(c4 * 4 + 1) * 128 + row] = v.y;
        featT[(c4 * 4 + 2) * 128 + row] = v.z;
        featT[(c4 * 4 + 3) * 128 + row] = v.w;
    }
    __syncthreads();

    // mainloop: acc2[n*4+cp] = packed cols (2cp, 2cp+1) of node n
    ull acc2[16];
#pragma unroll
    for (int j = 0; j < 16; j++) acc2[j] = 0ull;

#pragma unroll 4
    for (int k = 0; k < 128; k++) {
        float4 f = *(const float4*)&featT[k * 128 + tx * 4];
        ull fd[4];
        fd[0] = pack2(f.x); fd[1] = pack2(f.y);
        fd[2] = pack2(f.z); fd[3] = pack2(f.w);
        const ulonglong2* Wv = (const ulonglong2*)&Wsh[k * 64 + ty * 8];
        ulonglong2 wa = Wv[0];   // cols (0,1),(2,3)
        ulonglong2 wb = Wv[1];   // cols (4,5),(6,7)
#pragma unroll
        for (int n = 0; n < 4; n++) {
            fma2(acc2[n * 4 + 0], fd[n], wa.x);
            fma2(acc2[n * 4 + 1], fd[n], wa.y);
            fma2(acc2[n * 4 + 2], fd[n], wb.x);
            fma2(acc2[n * 4 + 3], fd[n], wb.y);
        }
    }

    // unpack accumulators
    float o[4][8];
#pragma unroll
    for (int n = 0; n < 4; n++)
#pragma unroll
        for (int cp = 0; cp < 4; cp++)
            unpack2(acc2[n * 4 + cp], o[n][2 * cp], o[n][2 * cp + 1]);

    // partial el/er: this thread's 8 cols lie entirely in head ty>>1
    const int head = ty >> 1;
#pragma unroll
    for (int n = 0; n < 4; n++) {
        float sl = 0.f, sr = 0.f;
#pragma unroll
        for (int c = 0; c < 8; c++) {
            int col = ty * 8 + c;
            sl += o[n][c] * alS[col];
            sr += o[n][c] * arS[col];
        }
        int node_l = tx * 4 + n;
        atomicAdd(&elS[node_l * 4 + head], sl);
        atomicAdd(&erS[node_l * 4 + head], sr);
    }

    // store h directly (two STG.128 per node)
    float* g_h_f = (float*)g_h;
#pragma unroll
    for (int n = 0; n < 4; n++) {
        int node = base + tx * 4 + n;
        if (node < n_nodes) {
            float* p = g_h_f + node * 64 + ty * 8;
            *(float4*)p       = make_float4(o[n][0], o[n][1], o[n][2], o[n][3]);
            *(float4*)(p + 4) = make_float4(o[n][4], o[n][5], o[n][6], o[n][7]);
        }
    }

    __syncthreads();
    if (tid < 128) {
        int node = base + tid;
        if (node < n_nodes) {
            g_el[node] = ((const float4*)elS)[tid];
            g_er[node] = ((const float4*)erS)[tid];
        }
    }
}

// ---------------- kernel: fused softmax + aggregation ------------------------
// one warp per node. ex computed lane-parallel (1 edge per lane), staged in
// smem; serial agg loop = shfl(s) + LDS(ex) + LDG(h) + 2 FFMA per edge.
__global__ __launch_bounds__(256)
void node_kernel(const float* __restrict__ bias, float* __restrict__ out,
                 int n_nodes) {
    __shared__ float sm_ex[8][128];   // [warp][edge*4 + head]
    const int gwarp = (blockIdx.x * blockDim.x + threadIdx.x) >> 5;
    const int w     = (threadIdx.x >> 5);
    const int lane  = threadIdx.x & 31;
    if (gwarp >= n_nodes) return;

    const int base = g_rowptr[gwarp];
    const int deg  = g_cnt[gwarp];
    const int hd   = lane >> 3;

    const float2 b2 = ((const float2*)bias)[lane];
    float2* outp = (float2*)out + (gwarp * 32 + lane);
    if (deg == 0) { *outp = b2; return; }

    const float4 er4 = g_er[gwarp];
    const float2* h2 = (const float2*)g_h;

    float2 acc  = make_float2(0.f, 0.f);
    float4 den4 = make_float4(0.f, 0.f, 0.f, 0.f);

    const int nb = (deg + 31) >> 5;
    int s_reg = (lane < deg) ? g_esrc[base + lane] : 0;
    for (int b = 0; b < nb; b++) {
        const int cur = s_reg;
        const int cnt = min(32, deg - b * 32);
        const int noff = (b + 1) * 32;
        if (b + 1 < nb)
            s_reg = (noff + lane < deg) ? g_esrc[base + noff + lane] : 0;

        // lane-parallel exp for this batch
        float4 ex = make_float4(0.f, 0.f, 0.f, 0.f);
        if (lane < cnt) {
            float4 a = g_el[cur];
            ex.x = __expf(leaky(a.x + er4.x));
            ex.y = __expf(leaky(a.y + er4.y));
            ex.z = __expf(leaky(a.z + er4.z));
            ex.w = __expf(leaky(a.w + er4.w));
        }
        den4.x += ex.x; den4.y += ex.y; den4.z += ex.z; den4.w += ex.w;
        __syncwarp();
        ((float4*)sm_ex[w])[lane] = ex;
        __syncwarp();

        // serial aggregation over the batch
#pragma unroll 8
        for (int i = 0; i < cnt; i++) {
            int s = __shfl_sync(FULL, cur, i);
            float a = sm_ex[w][i * 4 + hd];
            float2 v = h2[s * 32 + lane];
            acc.x += a * v.x;
            acc.y += a * v.y;
        }
    }

    // cross-lane denominator reduce (all 4 heads)
#pragma unroll
    for (int o = 16; o; o >>= 1) {
        den4.x += __shfl_xor_sync(FULL, den4.x, o);
        den4.y += __shfl_xor_sync(FULL, den4.y, o);
        den4.z += __shfl_xor_sync(FULL, den4.z, o);
        den4.w += __shfl_xor_sync(FULL, den4.w, o);
    }
    const float den = hd == 0 ? den4.x : hd == 1 ? den4.y : hd == 2 ? den4.z : den4.w;
    const float rd = 1.f / den;
    *outp = make_float2(acc.x * rd + b2.x, acc.y * rd + b2.y);
}

// ---------------- launcher --------------------------------------------------
extern "C" void kernel_launch(void* const* d_in, const int* in_sizes, int n_in,
                              void* d_out, int out_size) {
    const float* feat   = (const float*)d_in[0];
    const float* W      = (const float*)d_in[1];
    const float* attn_l = (const float*)d_in[2];
    const float* attn_r = (const float*)d_in[3];
    const float* bias   = (const float*)d_in[4];
    const int*   src    = (const int*)d_in[5];
    const int*   dst    = (const int*)d_in[6];
    float*       out    = (float*)d_out;

    const int n_nodes = in_sizes[0] / 128;
    const int n_edges = in_sizes[5];
    const int nb      = (n_nodes + 1023) / 1024;

    cudaFuncSetAttribute(gemm_kernel, cudaFuncAttributeMaxDynamicSharedMemorySize,
                         GEMM_SMEM_FLOATS * (int)sizeof(float));

    // gemm placed 4th: ncu captures launch #4
    zero_kernel<<<(n_nodes + 255) / 256, 256>>>(n_nodes);
    hist_kernel<<<(n_edges + 255) / 256, 256>>>(dst, n_edges);
    scan1_kernel<<<nb, 1024>>>(n_nodes);
    gemm_kernel<<<(n_nodes + 127) / 128, 256,
                  GEMM_SMEM_FLOATS * (int)sizeof(float)>>>(feat, W, attn_l,
                                                           attn_r, n_nodes);
    scan2_kernel<<<1, 128>>>(nb);
    scan3_kernel<<<nb, 1024>>>(n_nodes);
    scatter_kernel<<<(n_edges + 255) / 256, 256>>>(src, dst, n_edges);
    node_kernel<<<(n_nodes * 32 + 255) / 256, 256>>>(bias, out, n_nodes);
}

// round 7
// speedup vs baseline: 1.2327x; 1.0145x over previous
#include <cuda_runtime.h>
#include <cstdint>
#include <cfloat>

#define N_NODES_MAX 100000
#define N_EDGES_MAX 1600000
#define FULL 0xFFFFFFFFu

typedef unsigned long long ull;

// ---------------- scratch (static device globals) ---------------------------
__device__ float4  g_h[N_NODES_MAX * 16];     // [N,64] projected features
__device__ float4  g_el[N_NODES_MAX];         // [N,4]
__device__ float4  g_er[N_NODES_MAX];         // [N,4]
__device__ int     g_cnt[N_NODES_MAX];        // in-degree
__device__ int     g_fill[N_NODES_MAX];       // scatter cursors
__device__ int     g_rowptr[N_NODES_MAX];     // exclusive prefix of cnt
__device__ int     g_blksum[128];
__device__ int     g_esrc[N_EDGES_MAX];       // CSR: src node per slot

__device__ __forceinline__ float leaky(float x) { return x > 0.f ? x : 0.2f * x; }

__device__ __forceinline__ ull pack2(float f) {
    ull r;
    asm("mov.b64 %0, {%1, %1};" : "=l"(r) : "f"(f));
    return r;
}
__device__ __forceinline__ void fma2(ull& acc, ull a, ull b) {
    asm("fma.rn.f32x2 %0, %1, %2, %0;" : "+l"(acc) : "l"(a), "l"(b));
}
__device__ __forceinline__ void unpack2(ull v, float& lo, float& hi) {
    asm("mov.b64 {%0, %1}, %2;" : "=f"(lo), "=f"(hi) : "l"(v));
}

// ---------------- kernel: zero counters -------------------------------------
__global__ void zero_kernel(int n_nodes) {
    int i = blockIdx.x * blockDim.x + threadIdx.x;
    if (i < n_nodes) { g_cnt[i] = 0; g_fill[i] = 0; }
}

// ---------------- kernel: in-degree histogram -------------------------------
__global__ void hist_kernel(const int* __restrict__ dst, int n_edges) {
    int e = blockIdx.x * blockDim.x + threadIdx.x;
    if (e < n_edges) atomicAdd(&g_cnt[dst[e]], 1);
}

// ---------------- scan: rowptr = exclusive_scan(cnt) ------------------------
__global__ __launch_bounds__(1024) void scan1_kernel(int n) {
    __shared__ int sh[1024];
    int i = blockIdx.x * 1024 + threadIdx.x;
    int v = (i < n) ? g_cnt[i] : 0;
    sh[threadIdx.x] = v;
    __syncthreads();
    for (int off = 1; off < 1024; off <<= 1) {
        int t = (threadIdx.x >= off) ? sh[threadIdx.x - off] : 0;
        __syncthreads();
        sh[threadIdx.x] += t;
        __syncthreads();
    }
    if (i < n) g_rowptr[i] = sh[threadIdx.x] - v;
    if (threadIdx.x == 1023) g_blksum[blockIdx.x] = sh[1023];
}
// merged scan2+scan3: each block computes prefix of blksum below it, adds.
__global__ __launch_bounds__(1024) void scan23_kernel(int n, int nb) {
    __shared__ int sh[128];
    const int t = threadIdx.x;
    if (t < 128) sh[t] = (t < nb && t < (int)blockIdx.x) ? g_blksum[t] : 0;
    __syncthreads();
    // tree reduce 128 -> 1 (threads 0..127 participate)
    if (t < 64)  sh[t] += sh[t + 64];
    __syncthreads();
    if (t < 32) {
        int v = sh[t] + sh[t + 32];
#pragma unroll
        for (int o = 16; o; o >>= 1) v += __shfl_xor_sync(FULL, v, o);
        if (t == 0) sh[0] = v;
    }
    __syncthreads();
    const int off = sh[0];
    int i = blockIdx.x * 1024 + t;
    if (i < n) g_rowptr[i] += off;
}

// ---------------- kernel: CSR scatter ----------------------------------------
__global__ void scatter_kernel(const int* __restrict__ src,
                               const int* __restrict__ dst, int n_edges) {
    int e = blockIdx.x * blockDim.x + threadIdx.x;
    if (e >= n_edges) return;
    int d = dst[e];
    int r = atomicAdd(&g_fill[d], 1);
    g_esrc[g_rowptr[d] + r] = src[e];
}

// ---------------- kernel: h = feat @ W, el/er (k-chunked, f32x2) -------------
// 256 threads, tile = 128 nodes x 64 cols; featT staged in 32-k chunks (16KB)
// so smem/CTA ~53.8KB -> 4 CTAs/SM. Thread (tx,ty) owns nodes tx*4..+3,
// cols ty*8..+7. Per k-step: 3 LDS.128 + 16 FFMA2.
#define FEATT_F   (32 * 128)
#define GEMM_SMEM_FLOATS (FEATT_F + 128 * 64 + 64 + 64 + 512 + 512)
__global__ __launch_bounds__(256, 4)
void gemm_kernel(const float* __restrict__ feat, const float* __restrict__ W,
                 const float* __restrict__ attn_l, const float* __restrict__ attn_r,
                 int n_nodes) {
    extern __shared__ float smem[];
    float* featT = smem;                       // [k%32][node] 32x128
    float* Wsh   = smem + FEATT_F;             // [k][col]  128x64
    float* alS   = Wsh + 8192;                 // 64
    float* arS   = alS + 64;                   // 64
    float* elS   = arS + 64;                   // [node][head] 128x4
    float* erS   = elS + 512;                  // 128x4

    const int tid  = threadIdx.x;
    const int tx   = tid & 31;
    const int ty   = tid >> 5;
    const int base = blockIdx.x * 128;

    for (int i = tid; i < 128 * 64; i += 256) Wsh[i] = W[i];
    if (tid < 64) { alS[tid] = attn_l[tid]; arS[tid] = attn_r[tid]; }
    if (tid < 128) {
        float4 z = make_float4(0.f, 0.f, 0.f, 0.f);
        ((float4*)elS)[tid] = z;
        ((float4*)erS)[tid] = z;
    }

    ull acc2[16];
#pragma unroll
    for (int j = 0; j < 16; j++) acc2[j] = 0ull;

    const float4* feat4 = (const float4*)feat;
    const int row  = tid & 127;          // staging row (node within tile)
    const int c4b  = tid >> 7;           // staging k4 base (0..1)
    const int node_s = base + row;

    for (int c = 0; c < 4; c++) {
        if (c) __syncthreads();          // previous chunk fully consumed
        // stage chunk c: 128 nodes x 8 float4, 4 per thread
#pragma unroll
        for (int j = 0; j < 4; j++) {
            int c4 = c4b + j * 2;        // 0..7 within chunk
            float4 v = (node_s < n_nodes)
                         ? feat4[node_s * 32 + c * 8 + c4]
                         : make_float4(0.f, 0.f, 0.f, 0.f);
            featT[(c4 * 4 + 0) * 128 + row] = v.x;
            featT[(c4 * 4 + 1) * 128 + row] = v.y;
            featT[(c4 * 4 + 2) * 128 + row] = v.z;
            featT[(c4 * 4 + 3) * 128 + row] = v.w;
        }
        __syncthreads();

#pragma unroll 8
        for (int k = 0; k < 32; k++) {
            float4 f = *(const float4*)&featT[k * 128 + tx * 4];
            ull fd0 = pack2(f.x), fd1 = pack2(f.y);
            ull fd2 = pack2(f.z), fd3 = pack2(f.w);
            const ulonglong2* Wv =
                (const ulonglong2*)&Wsh[(c * 32 + k) * 64 + ty * 8];
            ulonglong2 wa = Wv[0];
            ulonglong2 wb = Wv[1];
            fma2(acc2[0],  fd0, wa.x); fma2(acc2[1],  fd0, wa.y);
            fma2(acc2[2],  fd0, wb.x); fma2(acc2[3],  fd0, wb.y);
            fma2(acc2[4],  fd1, wa.x); fma2(acc2[5],  fd1, wa.y);
            fma2(acc2[6],  fd1, wb.x); fma2(acc2[7],  fd1, wb.y);
            fma2(acc2[8],  fd2, wa.x); fma2(acc2[9],  fd2, wa.y);
            fma2(acc2[10], fd2, wb.x); fma2(acc2[11], fd2, wb.y);
            fma2(acc2[12], fd3, wa.x); fma2(acc2[13], fd3, wa.y);
            fma2(acc2[14], fd3, wb.x); fma2(acc2[15], fd3, wb.y);
        }
    }

    float o[4][8];
#pragma unroll
    for (int n = 0; n < 4; n++)
#pragma unroll
        for (int cp = 0; cp < 4; cp++)
            unpack2(acc2[n * 4 + cp], o[n][2 * cp], o[n][2 * cp + 1]);

    // partial el/er: this thread's 8 cols lie entirely in head ty>>1
    const int head = ty >> 1;
#pragma unroll
    for (int n = 0; n < 4; n++) {
        float sl = 0.f, sr = 0.f;
#pragma unroll
        for (int cc = 0; cc < 8; cc++) {
            int col = ty * 8 + cc;
            sl += o[n][cc] * alS[col];
            sr += o[n][cc] * arS[col];
        }
        int node_l = tx * 4 + n;
        atomicAdd(&elS[node_l * 4 + head], sl);
        atomicAdd(&erS[node_l * 4 + head], sr);
    }

    // store h (two STG.128 per node)
    float* g_h_f = (float*)g_h;
#pragma unroll
    for (int n = 0; n < 4; n++) {
        int node = base + tx * 4 + n;
        if (node < n_nodes) {
            float* p = g_h_f + node * 64 + ty * 8;
            *(float4*)p       = make_float4(o[n][0], o[n][1], o[n][2], o[n][3]);
            *(float4*)(p + 4) = make_float4(o[n][4], o[n][5], o[n][6], o[n][7]);
        }
    }

    __syncthreads();
    if (tid < 128) {
        int node = base + tid;
        if (node < n_nodes) {
            g_el[node] = ((const float4*)elS)[tid];
            g_er[node] = ((const float4*)erS)[tid];
        }
    }
}

// ---------------- kernel: fused softmax + aggregation ------------------------
// one warp per node. ex computed lane-parallel (1 edge per lane), staged in
// smem; serial agg loop = shfl(s) + LDS(ex) + LDG(h) + 2 FFMA per edge.
__global__ __launch_bounds__(256)
void node_kernel(const float* __restrict__ bias, float* __restrict__ out,
                 int n_nodes) {
    __shared__ float sm_ex[8][128];   // [warp][edge*4 + head]
    const int gwarp = (blockIdx.x * blockDim.x + threadIdx.x) >> 5;
    const int w     = (threadIdx.x >> 5);
    const int lane  = threadIdx.x & 31;
    if (gwarp >= n_nodes) return;

    const int base = g_rowptr[gwarp];
    const int deg  = g_cnt[gwarp];
    const int hd   = lane >> 3;

    const float2 b2 = ((const float2*)bias)[lane];
    float2* outp = (float2*)out + (gwarp * 32 + lane);
    if (deg == 0) { *outp = b2; return; }

    const float4 er4 = g_er[gwarp];
    const float2* h2 = (const float2*)g_h;

    float2 acc  = make_float2(0.f, 0.f);
    float4 den4 = make_float4(0.f, 0.f, 0.f, 0.f);

    const int nb = (deg + 31) >> 5;
    int s_reg = (lane < deg) ? g_esrc[base + lane] : 0;
    for (int b = 0; b < nb; b++) {
        const int cur = s_reg;
        const int cnt = min(32, deg - b * 32);
        const int noff = (b + 1) * 32;
        if (b + 1 < nb)
            s_reg = (noff + lane < deg) ? g_esrc[base + noff + lane] : 0;

        float4 ex = make_float4(0.f, 0.f, 0.f, 0.f);
        if (lane < cnt) {
            float4 a = g_el[cur];
            ex.x = __expf(leaky(a.x + er4.x));
            ex.y = __expf(leaky(a.y + er4.y));
            ex.z = __expf(leaky(a.z + er4.z));
            ex.w = __expf(leaky(a.w + er4.w));
        }
        den4.x += ex.x; den4.y += ex.y; den4.z += ex.z; den4.w += ex.w;
        __syncwarp();
        ((float4*)sm_ex[w])[lane] = ex;
        __syncwarp();

#pragma unroll 8
        for (int i = 0; i < cnt; i++) {
            int s = __shfl_sync(FULL, cur, i);
            float a = sm_ex[w][i * 4 + hd];
            float2 v = h2[s * 32 + lane];
            acc.x += a * v.x;
            acc.y += a * v.y;
        }
    }

#pragma unroll
    for (int o = 16; o; o >>= 1) {
        den4.x += __shfl_xor_sync(FULL, den4.x, o);
        den4.y += __shfl_xor_sync(FULL, den4.y, o);
        den4.z += __shfl_xor_sync(FULL, den4.z, o);
        den4.w += __shfl_xor_sync(FULL, den4.w, o);
    }
    const float den = hd == 0 ? den4.x : hd == 1 ? den4.y : hd == 2 ? den4.z : den4.w;
    const float rd = 1.f / den;
    *outp = make_float2(acc.x * rd + b2.x, acc.y * rd + b2.y);
}

// ---------------- launcher --------------------------------------------------
extern "C" void kernel_launch(void* const* d_in, const int* in_sizes, int n_in,
                              void* d_out, int out_size) {
    const float* feat   = (const float*)d_in[0];
    const float* W      = (const float*)d_in[1];
    const float* attn_l = (const float*)d_in[2];
    const float* attn_r = (const float*)d_in[3];
    const float* bias   = (const float*)d_in[4];
    const int*   src    = (const int*)d_in[5];
    const int*   dst    = (const int*)d_in[6];
    float*       out    = (float*)d_out;

    const int n_nodes = in_sizes[0] / 128;
    const int n_edges = in_sizes[5];
    const int nb      = (n_nodes + 1023) / 1024;

    cudaFuncSetAttribute(gemm_kernel, cudaFuncAttributeMaxDynamicSharedMemorySize,
                         GEMM_SMEM_FLOATS * (int)sizeof(float));

    // gemm placed 4th: ncu captures launch #4
    zero_kernel<<<(n_nodes + 255) / 256, 256>>>(n_nodes);
    hist_kernel<<<(n_edges + 255) / 256, 256>>>(dst, n_edges);
    scan1_kernel<<<nb, 1024>>>(n_nodes);
    gemm_kernel<<<(n_nodes + 127) / 128, 256,
                  GEMM_SMEM_FLOATS * (int)sizeof(float)>>>(feat, W, attn_l,
                                                           attn_r, n_nodes);
    scan23_kernel<<<nb, 1024>>>(n_nodes, nb);
    scatter_kernel<<<(n_edges + 255) / 256, 256>>>(src, dst, n_edges);
    node_kernel<<<(n_nodes * 32 + 255) / 256, 256>>>(bias, out, n_nodes);
}